// round 1
// baseline (speedup 1.0000x reference)
#include <cuda_runtime.h>

#define B_ 4
#define S_ 2048
#define D_ 1024
#define H_ 1024

// Scratch (allocation-free rule: __device__ globals)
__device__ float g_q[B_ * S_ * H_];                 // 32 MB
__device__ float g_k[B_ * S_ * H_];                 // 32 MB
__device__ float g_v[B_ * S_ * H_];                 // 32 MB
__device__ float g_p[(size_t)B_ * S_ * S_];         // 64 MB

// ---------------------------------------------------------------------------
// Tiled SGEMM: C = alpha * A @ op(B) + bias
//   TRANSB=0: B is [K,N] row-major (NN)
//   TRANSB=1: B is [N,K] row-major (NT, i.e. contract inner dims)
// Tile: 128x128x16, 256 threads, 8x8 per thread. No bounds checks —
// all problem dims are multiples of the tile sizes.
// ---------------------------------------------------------------------------
template <int TRANSB>
__global__ __launch_bounds__(256, 2) void sgemm128(
    const float* __restrict__ A, const float* __restrict__ Bm,
    float* __restrict__ C, const float* __restrict__ bias,
    float alpha, int K, int lda, int ldb, int ldc,
    long sA, long sB, long sC)
{
    __shared__ float As[16][132];   // [k][m], padded stride: conflict-free
    __shared__ float Bs[16][132];   // [k][n]

    const int t  = threadIdx.x;
    const int m0 = blockIdx.y << 7;
    const int n0 = blockIdx.x << 7;

    A  += (size_t)blockIdx.z * sA;
    Bm += (size_t)blockIdx.z * sB;
    C  += (size_t)blockIdx.z * sC;

    float acc[8][8];
#pragma unroll
    for (int i = 0; i < 8; i++)
#pragma unroll
        for (int j = 0; j < 8; j++) acc[i][j] = 0.f;

    const int tx = t & 15;   // n sub-tile
    const int ty = t >> 4;   // m sub-tile

    for (int k0 = 0; k0 < K; k0 += 16) {
        // ---- load A tile (128 rows x 16 k), transposed store ----
#pragma unroll
        for (int i = 0; i < 2; i++) {
            int idx = t + (i << 8);          // 0..511
            int r   = idx >> 2;              // 0..127
            int c   = (idx & 3) << 2;        // 0,4,8,12
            float4 va = *(const float4*)(A + (size_t)(m0 + r) * lda + k0 + c);
            As[c + 0][r] = va.x; As[c + 1][r] = va.y;
            As[c + 2][r] = va.z; As[c + 3][r] = va.w;

            if (TRANSB) {
                // B is [N,K]: same transpose pattern over n-rows
                float4 vb = *(const float4*)(Bm + (size_t)(n0 + r) * ldb + k0 + c);
                Bs[c + 0][r] = vb.x; Bs[c + 1][r] = vb.y;
                Bs[c + 2][r] = vb.z; Bs[c + 3][r] = vb.w;
            } else {
                // B is [K,N]: direct float4 rows
                int rb = idx >> 5;            // 0..15
                int cb = (idx & 31) << 2;     // 0..124
                float4 vb = *(const float4*)(Bm + (size_t)(k0 + rb) * ldb + n0 + cb);
                *(float4*)&Bs[rb][cb] = vb;
            }
        }
        __syncthreads();

        // ---- compute ----
#pragma unroll
        for (int k = 0; k < 16; k++) {
            float a[8], b[8];
            *(float4*)(a)     = *(const float4*)&As[k][ty * 8];
            *(float4*)(a + 4) = *(const float4*)&As[k][ty * 8 + 4];
            *(float4*)(b)     = *(const float4*)&Bs[k][tx * 8];
            *(float4*)(b + 4) = *(const float4*)&Bs[k][tx * 8 + 4];
#pragma unroll
            for (int i = 0; i < 8; i++)
#pragma unroll
                for (int j = 0; j < 8; j++)
                    acc[i][j] = fmaf(a[i], b[j], acc[i][j]);
        }
        __syncthreads();
    }

    // ---- epilogue ----
    float bv[8];
#pragma unroll
    for (int j = 0; j < 8; j++)
        bv[j] = bias ? bias[n0 + tx * 8 + j] : 0.f;

#pragma unroll
    for (int i = 0; i < 8; i++) {
        float* cp = C + (size_t)(m0 + ty * 8 + i) * ldc + n0 + tx * 8;
        float4 o0, o1;
        o0.x = acc[i][0] * alpha + bv[0];
        o0.y = acc[i][1] * alpha + bv[1];
        o0.z = acc[i][2] * alpha + bv[2];
        o0.w = acc[i][3] * alpha + bv[3];
        o1.x = acc[i][4] * alpha + bv[4];
        o1.y = acc[i][5] * alpha + bv[5];
        o1.z = acc[i][6] * alpha + bv[6];
        o1.w = acc[i][7] * alpha + bv[7];
        *(float4*)(cp)     = o0;
        *(float4*)(cp + 4) = o1;
    }
}

// ---------------------------------------------------------------------------
// Row softmax over 2048 columns. One block (256 threads) per row; each
// thread owns 8 elements held in registers across the three phases.
// ---------------------------------------------------------------------------
__global__ __launch_bounds__(256) void softmax2048(float* __restrict__ P)
{
    float4* p = (float4*)(P + (size_t)blockIdx.x * 2048);
    const int t = threadIdx.x;

    float4 v0 = p[t];
    float4 v1 = p[t + 256];

    float m = fmaxf(fmaxf(fmaxf(v0.x, v0.y), fmaxf(v0.z, v0.w)),
                    fmaxf(fmaxf(v1.x, v1.y), fmaxf(v1.z, v1.w)));

    __shared__ float red[256];
    red[t] = m;
    __syncthreads();
#pragma unroll
    for (int s = 128; s > 0; s >>= 1) {
        if (t < s) red[t] = fmaxf(red[t], red[t + s]);
        __syncthreads();
    }
    m = red[0];
    __syncthreads();

    v0.x = expf(v0.x - m); v0.y = expf(v0.y - m);
    v0.z = expf(v0.z - m); v0.w = expf(v0.w - m);
    v1.x = expf(v1.x - m); v1.y = expf(v1.y - m);
    v1.z = expf(v1.z - m); v1.w = expf(v1.w - m);

    float sum = (v0.x + v0.y + v0.z + v0.w) + (v1.x + v1.y + v1.z + v1.w);
    red[t] = sum;
    __syncthreads();
#pragma unroll
    for (int s = 128; s > 0; s >>= 1) {
        if (t < s) red[t] += red[t + s];
        __syncthreads();
    }
    float inv = 1.f / red[0];

    v0.x *= inv; v0.y *= inv; v0.z *= inv; v0.w *= inv;
    v1.x *= inv; v1.y *= inv; v1.z *= inv; v1.w *= inv;
    p[t]       = v0;
    p[t + 256] = v1;
}

// ---------------------------------------------------------------------------
extern "C" void kernel_launch(void* const* d_in, const int* in_sizes, int n_in,
                              void* d_out, int out_size)
{
    const float* x  = (const float*)d_in[0];
    const float* Wq = (const float*)d_in[1];
    const float* bq = (const float*)d_in[2];
    const float* Wk = (const float*)d_in[3];
    const float* bk = (const float*)d_in[4];
    const float* Wv = (const float*)d_in[5];
    const float* bv = (const float*)d_in[6];
    float* out = (float*)d_out;

    float *q, *k, *v, *p;
    cudaGetSymbolAddress((void**)&q, g_q);
    cudaGetSymbolAddress((void**)&k, g_k);
    cudaGetSymbolAddress((void**)&v, g_v);
    cudaGetSymbolAddress((void**)&p, g_p);

    const int MS = B_ * S_;          // 8192
    const float inv_dk = 0.03125f;   // 1/sqrt(1024)

    // QKV projections: [8192,1024] @ [1024,1024] + bias
    dim3 gProj(H_ / 128, MS / 128, 1);
    sgemm128<0><<<gProj, 256>>>(x, Wq, q, bq, 1.f, D_, D_, H_, H_, 0, 0, 0);
    sgemm128<0><<<gProj, 256>>>(x, Wk, k, bk, 1.f, D_, D_, H_, H_, 0, 0, 0);
    sgemm128<0><<<gProj, 256>>>(x, Wv, v, bv, 1.f, D_, D_, H_, H_, 0, 0, 0);

    // scores[b] = (q[b] @ k[b]^T) / 32 : per-b 2048x2048, K=1024 (NT)
    dim3 gScore(S_ / 128, S_ / 128, B_);
    sgemm128<1><<<gScore, 256>>>(q, k, p, nullptr, inv_dk,
                                 H_, H_, H_, S_,
                                 (long)S_ * H_, (long)S_ * H_, (long)S_ * S_);

    // softmax over last dim
    softmax2048<<<B_ * S_, 256>>>(p);

    // out[b] = probs[b] @ v[b] : per-b 2048x1024, K=2048 (NN)
    dim3 gPV(H_ / 128, S_ / 128, B_);
    sgemm128<0><<<gPV, 256>>>(p, v, out, nullptr, 1.f,
                              S_, S_, H_, H_,
                              (long)S_ * S_, (long)S_ * H_, (long)S_ * H_);
}

// round 3
// speedup vs baseline: 2.7563x; 2.7563x over previous
#include <cuda_runtime.h>
#include <cstdint>

#define B_ 4
#define S_ 2048
#define D_ 1024
#define H_ 1024

// Scratch (allocation-free rule: __device__ globals)
__device__ __align__(128) float g_q[B_ * S_ * H_];          // 32 MB
__device__ __align__(128) float g_k[B_ * S_ * H_];          // 32 MB
__device__ __align__(128) float g_v[B_ * S_ * H_];          // 32 MB
__device__ __align__(128) float g_p[(size_t)B_ * S_ * S_];  // 64 MB

__device__ __forceinline__ uint32_t smem_u32(const void* p) {
    uint32_t a;
    asm("{ .reg .u64 t; cvta.to.shared.u64 t, %1; cvt.u32.u64 %0, t; }" : "=r"(a) : "l"(p));
    return a;
}
__device__ __forceinline__ void cp16(uint32_t dst, const void* src) {
    asm volatile("cp.async.ca.shared.global [%0], [%1], 16;" :: "r"(dst), "l"(src));
}
__device__ __forceinline__ uint32_t f2tf32(float f) {
    uint32_t u;
    asm("cvt.rna.tf32.f32 %0, %1;" : "=r"(u) : "f"(f));
    return u;
}
__device__ __forceinline__ void mma_tf32(float* d, const uint32_t* a, const uint32_t* b) {
    asm volatile(
        "mma.sync.aligned.m16n8k8.row.col.f32.tf32.tf32.f32 "
        "{%0,%1,%2,%3}, {%4,%5,%6,%7}, {%8,%9}, {%0,%1,%2,%3};"
        : "+f"(d[0]), "+f"(d[1]), "+f"(d[2]), "+f"(d[3])
        : "r"(a[0]), "r"(a[1]), "r"(a[2]), "r"(a[3]), "r"(b[0]), "r"(b[1]));
}

// ---------------------------------------------------------------------------
// TF32 GEMM: C = alpha * A @ op(B) + bias
//   TRANSB=0: B is [K,N] row-major (NN)        TRANSB=1: B is [N,K] row-major (NT)
// Block 128x128xK16, 8 warps of 64x32, mma.m16n8k8, cp.async 2-stage pipeline.
// A smem: [m][k] stride 20 (conflict-free frag loads).
// B smem: NT -> [n][k] stride 20; NN -> [k][n] stride 136 (conflict-free).
// ---------------------------------------------------------------------------
#define SA 20
#define SB0 136

template <int TRANSB>
__global__ __launch_bounds__(256, 2) void mma_gemm(
    const float* __restrict__ A, const float* __restrict__ Bm,
    float* __restrict__ C, const float* __restrict__ bias,
    float alpha, int K, int lda, int ldb, int ldc,
    long sA_, long sB_, long sC_)
{
    __shared__ __align__(128) float As[2][128 * SA];
    __shared__ __align__(128) float Bs[2][2560];   // NT: 128*20=2560; NN: 16*136=2176

    const int tid  = threadIdx.x;
    const int warp = tid >> 5, lane = tid & 31;
    const int g = lane >> 2, tg = lane & 3;
    const int wm0 = (warp & 1) * 64;
    const int wn0 = (warp >> 1) * 32;
    const int m0 = blockIdx.y << 7, n0 = blockIdx.x << 7;

    const float* pA = A + (size_t)blockIdx.z * sA_ + (size_t)m0 * lda;
    const float* pB = Bm + (size_t)blockIdx.z * sB_ + (TRANSB ? (size_t)n0 * ldb : (size_t)n0);

    const uint32_t asb = smem_u32(&As[0][0]);
    const uint32_t bsb = smem_u32(&Bs[0][0]);

    float acc[4][4][4];
#pragma unroll
    for (int i = 0; i < 4; i++)
#pragma unroll
        for (int j = 0; j < 4; j++)
#pragma unroll
            for (int r = 0; r < 4; r++) acc[i][j][r] = 0.f;

    const int NC = K >> 4;

    // ---- stage loader ----
    auto load_stage = [&](int s, int c) {
        const int k0 = c << 4;
        uint32_t ad = asb + s * (128 * SA * 4);
        uint32_t bd = bsb + s * (2560 * 4);
#pragma unroll
        for (int i = 0; i < 2; i++) {
            int idx = tid + (i << 8);
            int row = idx >> 2, seg = idx & 3;      // A: 128 rows x 4 segs
            cp16(ad + (row * SA + seg * 4) * 4, pA + (size_t)row * lda + k0 + seg * 4);
            if (TRANSB) {
                cp16(bd + (row * SA + seg * 4) * 4, pB + (size_t)row * ldb + k0 + seg * 4);
            } else {
                int rb = idx >> 5, sb2 = idx & 31;  // B: 16 k-rows x 32 segs
                cp16(bd + (rb * SB0 + sb2 * 4) * 4, pB + (size_t)(k0 + rb) * ldb + sb2 * 4);
            }
        }
    };

    load_stage(0, 0);
    asm volatile("cp.async.commit_group;");

    for (int c = 0; c < NC; c++) {
        if (c + 1 < NC) load_stage((c + 1) & 1, c + 1);
        asm volatile("cp.async.commit_group;");
        asm volatile("cp.async.wait_group 1;");
        __syncthreads();

        const float* as = As[c & 1];
        const float* bs = Bs[c & 1];
#pragma unroll
        for (int kk = 0; kk < 16; kk += 8) {
            uint32_t af[4][4];
#pragma unroll
            for (int mt = 0; mt < 4; mt++) {
                int m = wm0 + mt * 16 + g;
                af[mt][0] = f2tf32(as[m * SA + kk + tg]);
                af[mt][1] = f2tf32(as[(m + 8) * SA + kk + tg]);
                af[mt][2] = f2tf32(as[m * SA + kk + tg + 4]);
                af[mt][3] = f2tf32(as[(m + 8) * SA + kk + tg + 4]);
            }
            uint32_t bf[4][2];
#pragma unroll
            for (int nt = 0; nt < 4; nt++) {
                int n = wn0 + nt * 8 + g;
                if (TRANSB) {
                    bf[nt][0] = f2tf32(bs[n * SA + kk + tg]);
                    bf[nt][1] = f2tf32(bs[n * SA + kk + tg + 4]);
                } else {
                    bf[nt][0] = f2tf32(bs[(kk + tg) * SB0 + n]);
                    bf[nt][1] = f2tf32(bs[(kk + tg + 4) * SB0 + n]);
                }
            }
#pragma unroll
            for (int mt = 0; mt < 4; mt++)
#pragma unroll
                for (int nt = 0; nt < 4; nt++)
                    mma_tf32(acc[mt][nt], af[mt], bf[nt]);
        }
        __syncthreads();
    }

    // ---- epilogue: direct float2 stores ----
    float* pC = C + (size_t)blockIdx.z * sC_;
#pragma unroll
    for (int nt = 0; nt < 4; nt++) {
        const int col = n0 + wn0 + nt * 8 + 2 * tg;
        float2 bv = make_float2(0.f, 0.f);
        if (bias) bv = *(const float2*)&bias[col];
#pragma unroll
        for (int mt = 0; mt < 4; mt++) {
            int row = m0 + wm0 + mt * 16 + g;
            float2 v0, v1;
            v0.x = acc[mt][nt][0] * alpha + bv.x;
            v0.y = acc[mt][nt][1] * alpha + bv.y;
            v1.x = acc[mt][nt][2] * alpha + bv.x;
            v1.y = acc[mt][nt][3] * alpha + bv.y;
            *(float2*)&pC[(size_t)row * ldc + col]       = v0;
            *(float2*)&pC[(size_t)(row + 8) * ldc + col] = v1;
        }
    }
}

// ---------------------------------------------------------------------------
// Row softmax over 2048 columns, in place. One block (256 threads) per row.
// ---------------------------------------------------------------------------
__global__ __launch_bounds__(256) void softmax2048(float* __restrict__ P)
{
    float4* p = (float4*)(P + (size_t)blockIdx.x * 2048);
    const int t = threadIdx.x;

    float4 v0 = p[t];
    float4 v1 = p[t + 256];

    float m = fmaxf(fmaxf(fmaxf(v0.x, v0.y), fmaxf(v0.z, v0.w)),
                    fmaxf(fmaxf(v1.x, v1.y), fmaxf(v1.z, v1.w)));

    __shared__ float red[256];
    red[t] = m;
    __syncthreads();
#pragma unroll
    for (int s = 128; s > 0; s >>= 1) {
        if (t < s) red[t] = fmaxf(red[t], red[t + s]);
        __syncthreads();
    }
    m = red[0];
    __syncthreads();

    v0.x = expf(v0.x - m); v0.y = expf(v0.y - m);
    v0.z = expf(v0.z - m); v0.w = expf(v0.w - m);
    v1.x = expf(v1.x - m); v1.y = expf(v1.y - m);
    v1.z = expf(v1.z - m); v1.w = expf(v1.w - m);

    float sum = (v0.x + v0.y + v0.z + v0.w) + (v1.x + v1.y + v1.z + v1.w);
    red[t] = sum;
    __syncthreads();
#pragma unroll
    for (int s = 128; s > 0; s >>= 1) {
        if (t < s) red[t] += red[t + s];
        __syncthreads();
    }
    float inv = 1.f / red[0];

    v0.x *= inv; v0.y *= inv; v0.z *= inv; v0.w *= inv;
    v1.x *= inv; v1.y *= inv; v1.z *= inv; v1.w *= inv;
    p[t]       = v0;
    p[t + 256] = v1;
}

// ---------------------------------------------------------------------------
extern "C" void kernel_launch(void* const* d_in, const int* in_sizes, int n_in,
                              void* d_out, int out_size)
{
    const float* x  = (const float*)d_in[0];
    const float* Wq = (const float*)d_in[1];
    const float* bq = (const float*)d_in[2];
    const float* Wk = (const float*)d_in[3];
    const float* bk = (const float*)d_in[4];
    const float* Wv = (const float*)d_in[5];
    const float* bv = (const float*)d_in[6];
    float* out = (float*)d_out;

    float *q, *k, *v, *p;
    cudaGetSymbolAddress((void**)&q, g_q);
    cudaGetSymbolAddress((void**)&k, g_k);
    cudaGetSymbolAddress((void**)&v, g_v);
    cudaGetSymbolAddress((void**)&p, g_p);

    const float inv_dk = 0.03125f;   // 1/sqrt(1024)

    // QKV projections: [8192,1024] @ [1024,1024] + bias  (NN)
    dim3 gProj(H_ / 128, (B_ * S_) / 128, 1);
    mma_gemm<0><<<gProj, 256>>>(x, Wq, q, bq, 1.f, D_, D_, H_, H_, 0, 0, 0);
    mma_gemm<0><<<gProj, 256>>>(x, Wk, k, bk, 1.f, D_, D_, H_, H_, 0, 0, 0);
    mma_gemm<0><<<gProj, 256>>>(x, Wv, v, bv, 1.f, D_, D_, H_, H_, 0, 0, 0);

    // scores[b] = (q[b] @ k[b]^T) / 32 : per-b 2048x2048, K=1024 (NT)
    dim3 gScore(S_ / 128, S_ / 128, B_);
    mma_gemm<1><<<gScore, 256>>>(q, k, p, nullptr, inv_dk,
                                 H_, H_, H_, S_,
                                 (long)S_ * H_, (long)S_ * H_, (long)S_ * S_);

    softmax2048<<<B_ * S_, 256>>>(p);

    // out[b] = probs[b] @ v[b] : per-b 2048x1024, K=2048 (NN)
    dim3 gPV(H_ / 128, S_ / 128, B_);
    mma_gemm<0><<<gPV, 256>>>(p, v, out, nullptr, 1.f,
                              S_, S_, H_, H_,
                              (long)S_ * S_, (long)S_ * H_, (long)S_ * H_);
}

// round 4
// speedup vs baseline: 2.9323x; 1.0639x over previous
#include <cuda_runtime.h>
#include <cstdint>

#define B_ 4
#define S_ 2048
#define D_ 1024
#define H_ 1024

// Scratch (allocation-free rule: __device__ globals)
__device__ __align__(128) float g_xr[B_ * S_ * D_];         // x rounded+permuted
__device__ __align__(128) float g_wr[3 * D_ * H_];          // W rounded (natural)
__device__ __align__(128) float g_q[B_ * S_ * H_];          // q rounded+permuted
__device__ __align__(128) float g_k[B_ * S_ * H_];          // k rounded+permuted
__device__ __align__(128) float g_v[B_ * S_ * H_];          // v rounded (natural)
__device__ __align__(128) float g_p[(size_t)B_ * S_ * S_];  // scores / probs

__device__ __forceinline__ uint32_t smem_u32(const void* p) {
    uint32_t a;
    asm("{ .reg .u64 t; cvta.to.shared.u64 t, %1; cvt.u32.u64 %0, t; }" : "=r"(a) : "l"(p));
    return a;
}
__device__ __forceinline__ void cp16(uint32_t dst, const void* src) {
    asm volatile("cp.async.ca.shared.global [%0], [%1], 16;" :: "r"(dst), "l"(src));
}
__device__ __forceinline__ float rtf32(float f) {
    uint32_t u;
    asm("cvt.rna.tf32.f32 %0, %1;" : "=r"(u) : "f"(f));
    return __uint_as_float(u);
}
__device__ __forceinline__ void mma_tf32(float* d, const uint32_t* a, const uint32_t* b) {
    asm volatile(
        "mma.sync.aligned.m16n8k8.row.col.f32.tf32.tf32.f32 "
        "{%0,%1,%2,%3}, {%4,%5,%6,%7}, {%8,%9}, {%0,%1,%2,%3};"
        : "+f"(d[0]), "+f"(d[1]), "+f"(d[2]), "+f"(d[3])
        : "r"(a[0]), "r"(a[1]), "r"(a[2]), "r"(a[3]), "r"(b[0]), "r"(b[1]));
}

// ---------------------------------------------------------------------------
// TF32 GEMM over PRE-ROUNDED (and, for A / NT-B, k-permuted) operands.
//   A gmem: [M,K], K permuted in 8-groups: pos = 2(k&3)+(k>>2)
//   TRANSB=1: B gmem [N,K], same permutation   TRANSB=0: B gmem [K,N] natural
// Smem A / NT-B: row stride 24 words (16 data + 8 pad) -> conflict-free LDS.64.
// EMODE: 0 = plain store (alpha)   1 = round + k-permute store (+bias)
//        2 = round store (+bias)
// ---------------------------------------------------------------------------
#define STA 24
#define SBN 136

template <int TRANSB, int EMODE>
__global__ __launch_bounds__(256, 2) void mma_gemm(
    const float* __restrict__ A, const float* __restrict__ Bm,
    float* __restrict__ C, const float* __restrict__ bias,
    float alpha, int K, int lda, int ldb, int ldc,
    long sA_, long sB_, long sC_)
{
    __shared__ __align__(128) float As[2][128 * STA];
    __shared__ __align__(128) float Bs[2][TRANSB ? 128 * STA : 16 * SBN];

    const int tid  = threadIdx.x;
    const int warp = tid >> 5, lane = tid & 31;
    const int g = lane >> 2, tg = lane & 3;
    const int wm0 = (warp & 1) * 64;
    const int wn0 = (warp >> 1) * 32;
    const int m0 = blockIdx.y << 7, n0 = blockIdx.x << 7;

    const float* pA = A + (size_t)blockIdx.z * sA_ + (size_t)m0 * lda;
    const float* pB = Bm + (size_t)blockIdx.z * sB_ + (TRANSB ? (size_t)n0 * ldb : (size_t)n0);

    const uint32_t asb = smem_u32(&As[0][0]);
    const uint32_t bsb = smem_u32(&Bs[0][0]);
    const uint32_t bstg = (TRANSB ? 128 * STA : 16 * SBN) * 4;

    float acc[4][4][4];
#pragma unroll
    for (int i = 0; i < 4; i++)
#pragma unroll
        for (int j = 0; j < 4; j++)
#pragma unroll
            for (int r = 0; r < 4; r++) acc[i][j][r] = 0.f;

    const int NC = K >> 4;

    auto load_stage = [&](int s, int c) {
        const int k0 = c << 4;
        uint32_t ad = asb + s * (128 * STA * 4);
        uint32_t bd = bsb + s * bstg;
#pragma unroll
        for (int i = 0; i < 2; i++) {
            int idx = tid + (i << 8);
            int row = idx >> 2, seg = idx & 3;      // A: 128 rows x 4 x 16B
            cp16(ad + (row * STA + seg * 4) * 4, pA + (size_t)row * lda + k0 + seg * 4);
            if (TRANSB) {
                cp16(bd + (row * STA + seg * 4) * 4, pB + (size_t)row * ldb + k0 + seg * 4);
            } else {
                int rb = idx >> 5, sb2 = idx & 31;  // B: 16 k-rows x 32 x 16B
                cp16(bd + (rb * SBN + sb2 * 4) * 4, pB + (size_t)(k0 + rb) * ldb + sb2 * 4);
            }
        }
    };

    load_stage(0, 0);
    asm volatile("cp.async.commit_group;");

    for (int c = 0; c < NC; c++) {
        if (c + 1 < NC) load_stage((c + 1) & 1, c + 1);
        asm volatile("cp.async.commit_group;");
        asm volatile("cp.async.wait_group 1;");
        __syncthreads();

        const float* as = As[c & 1];
        const float* bs = Bs[c & 1];
#pragma unroll
        for (int kk = 0; kk < 16; kk += 8) {
            uint32_t af[4][4];
#pragma unroll
            for (int mt = 0; mt < 4; mt++) {
                int m = wm0 + mt * 16 + g;
                uint2 v0 = *(const uint2*)&as[m * STA + kk + 2 * tg];        // k+tg, k+tg+4
                uint2 v1 = *(const uint2*)&as[(m + 8) * STA + kk + 2 * tg];
                af[mt][0] = v0.x; af[mt][1] = v1.x;
                af[mt][2] = v0.y; af[mt][3] = v1.y;
            }
            uint32_t bf[4][2];
#pragma unroll
            for (int nt = 0; nt < 4; nt++) {
                int n = wn0 + nt * 8 + g;
                if (TRANSB) {
                    uint2 v = *(const uint2*)&bs[n * STA + kk + 2 * tg];
                    bf[nt][0] = v.x; bf[nt][1] = v.y;
                } else {
                    bf[nt][0] = __float_as_uint(bs[(kk + tg) * SBN + n]);
                    bf[nt][1] = __float_as_uint(bs[(kk + tg + 4) * SBN + n]);
                }
            }
#pragma unroll
            for (int mt = 0; mt < 4; mt++)
#pragma unroll
                for (int nt = 0; nt < 4; nt++)
                    mma_tf32(acc[mt][nt], af[mt], bf[nt]);
        }
        __syncthreads();
    }

    // ---- epilogue ----
    float* pC = C + (size_t)blockIdx.z * sC_;
#pragma unroll
    for (int nt = 0; nt < 4; nt++) {
        const int col = n0 + wn0 + nt * 8 + 2 * tg;
        float2 bv = make_float2(0.f, 0.f);
        if (EMODE != 0 && bias) bv = *(const float2*)&bias[col];
        // permuted column positions for EMODE 1 (within the 8-group)
        const int j0 = 2 * tg, j1 = 2 * tg + 1;
        const int p0 = 2 * (j0 & 3) + (j0 >> 2);
        const int p1 = 2 * (j1 & 3) + (j1 >> 2);
        const int colbase = n0 + wn0 + nt * 8;
#pragma unroll
        for (int mt = 0; mt < 4; mt++) {
            int row = m0 + wm0 + mt * 16 + g;
#pragma unroll
            for (int h = 0; h < 2; h++) {
                int r = row + h * 8;
                float vx = acc[mt][nt][2 * h]     * alpha + bv.x;
                float vy = acc[mt][nt][2 * h + 1] * alpha + bv.y;
                if (EMODE == 0) {
                    *(float2*)&pC[(size_t)r * ldc + col] = make_float2(vx, vy);
                } else if (EMODE == 1) {
                    pC[(size_t)r * ldc + colbase + p0] = rtf32(vx);
                    pC[(size_t)r * ldc + colbase + p1] = rtf32(vy);
                } else {
                    *(float2*)&pC[(size_t)r * ldc + col] = make_float2(rtf32(vx), rtf32(vy));
                }
            }
        }
    }
}

// ---------------------------------------------------------------------------
// Prep: round(+permute) copies
// ---------------------------------------------------------------------------
__global__ void roundperm(const float* __restrict__ in, float* __restrict__ out, int n8)
{
    int i = blockIdx.x * blockDim.x + threadIdx.x;
    if (i >= n8) return;
    const float4* s = (const float4*)(in + (size_t)i * 8);
    float4 a = s[0], b = s[1];
    float e0 = rtf32(a.x), e1 = rtf32(a.y), e2 = rtf32(a.z), e3 = rtf32(a.w);
    float e4 = rtf32(b.x), e5 = rtf32(b.y), e6 = rtf32(b.z), e7 = rtf32(b.w);
    float4* d = (float4*)(out + (size_t)i * 8);
    d[0] = make_float4(e0, e4, e1, e5);   // pos 0..3 hold k = 0,4,1,5
    d[1] = make_float4(e2, e6, e3, e7);   // pos 4..7 hold k = 2,6,3,7
}

__global__ void roundcopy(const float* __restrict__ in, float* __restrict__ out, int n4)
{
    int i = blockIdx.x * blockDim.x + threadIdx.x;
    if (i >= n4) return;
    float4 v = ((const float4*)in)[i];
    ((float4*)out)[i] = make_float4(rtf32(v.x), rtf32(v.y), rtf32(v.z), rtf32(v.w));
}

// ---------------------------------------------------------------------------
// Row softmax over 2048, in place; output rounded to tf32 and k-permuted.
// Thread t owns one full 8-group: cols 8t..8t+7.
// ---------------------------------------------------------------------------
__global__ __launch_bounds__(256) void softmax2048(float* __restrict__ P)
{
    float4* p = (float4*)(P + (size_t)blockIdx.x * 2048);
    const int t = threadIdx.x;

    float4 v0 = p[2 * t];
    float4 v1 = p[2 * t + 1];

    float m = fmaxf(fmaxf(fmaxf(v0.x, v0.y), fmaxf(v0.z, v0.w)),
                    fmaxf(fmaxf(v1.x, v1.y), fmaxf(v1.z, v1.w)));

    __shared__ float red[256];
    red[t] = m;
    __syncthreads();
#pragma unroll
    for (int s = 128; s > 0; s >>= 1) {
        if (t < s) red[t] = fmaxf(red[t], red[t + s]);
        __syncthreads();
    }
    m = red[0];
    __syncthreads();

    v0.x = expf(v0.x - m); v0.y = expf(v0.y - m);
    v0.z = expf(v0.z - m); v0.w = expf(v0.w - m);
    v1.x = expf(v1.x - m); v1.y = expf(v1.y - m);
    v1.z = expf(v1.z - m); v1.w = expf(v1.w - m);

    float sum = (v0.x + v0.y + v0.z + v0.w) + (v1.x + v1.y + v1.z + v1.w);
    red[t] = sum;
    __syncthreads();
#pragma unroll
    for (int s = 128; s > 0; s >>= 1) {
        if (t < s) red[t] += red[t + s];
        __syncthreads();
    }
    float inv = 1.f / red[0];

    float e0 = rtf32(v0.x * inv), e1 = rtf32(v0.y * inv);
    float e2 = rtf32(v0.z * inv), e3 = rtf32(v0.w * inv);
    float e4 = rtf32(v1.x * inv), e5 = rtf32(v1.y * inv);
    float e6 = rtf32(v1.z * inv), e7 = rtf32(v1.w * inv);
    p[2 * t]     = make_float4(e0, e4, e1, e5);
    p[2 * t + 1] = make_float4(e2, e6, e3, e7);
}

// ---------------------------------------------------------------------------
extern "C" void kernel_launch(void* const* d_in, const int* in_sizes, int n_in,
                              void* d_out, int out_size)
{
    const float* x  = (const float*)d_in[0];
    const float* Wq = (const float*)d_in[1];
    const float* bq = (const float*)d_in[2];
    const float* Wk = (const float*)d_in[3];
    const float* bk = (const float*)d_in[4];
    const float* Wv = (const float*)d_in[5];
    const float* bv = (const float*)d_in[6];
    float* out = (float*)d_out;

    float *xr, *wr, *q, *k, *v, *p;
    cudaGetSymbolAddress((void**)&xr, g_xr);
    cudaGetSymbolAddress((void**)&wr, g_wr);
    cudaGetSymbolAddress((void**)&q, g_q);
    cudaGetSymbolAddress((void**)&k, g_k);
    cudaGetSymbolAddress((void**)&v, g_v);
    cudaGetSymbolAddress((void**)&p, g_p);

    const float inv_dk = 0.03125f;   // 1/sqrt(1024)

    // prep: round+permute x; round W
    roundperm<<<(1048576 + 255) / 256, 256>>>(x, xr, 1048576);
    roundcopy<<<(262144 + 255) / 256, 256>>>(Wq, wr,           262144);
    roundcopy<<<(262144 + 255) / 256, 256>>>(Wk, wr + 1048576, 262144);
    roundcopy<<<(262144 + 255) / 256, 256>>>(Wv, wr + 2097152, 262144);

    // QKV projections: [8192,1024] @ [1024,1024] + bias  (NN)
    dim3 gProj(H_ / 128, (B_ * S_) / 128, 1);
    mma_gemm<0, 1><<<gProj, 256>>>(xr, wr,           q, bq, 1.f, D_, D_, H_, H_, 0, 0, 0);
    mma_gemm<0, 1><<<gProj, 256>>>(xr, wr + 1048576, k, bk, 1.f, D_, D_, H_, H_, 0, 0, 0);
    mma_gemm<0, 2><<<gProj, 256>>>(xr, wr + 2097152, v, bv, 1.f, D_, D_, H_, H_, 0, 0, 0);

    // scores[b] = (q[b] @ k[b]^T) / 32 : per-b 2048x2048, K=1024 (NT)
    dim3 gScore(S_ / 128, S_ / 128, B_);
    mma_gemm<1, 0><<<gScore, 256>>>(q, k, p, nullptr, inv_dk,
                                    H_, H_, H_, S_,
                                    (long)S_ * H_, (long)S_ * H_, (long)S_ * S_);

    softmax2048<<<B_ * S_, 256>>>(p);

    // out[b] = probs[b] @ v[b] : per-b 2048x1024, K=2048 (NN)
    dim3 gPV(H_ / 128, S_ / 128, B_);
    mma_gemm<0, 0><<<gPV, 256>>>(p, v, out, nullptr, 1.f,
                                 S_, S_, H_, H_,
                                 (long)S_ * S_, (long)S_ * H_, (long)S_ * H_);
}

// round 5
// speedup vs baseline: 6.6150x; 2.2559x over previous
#include <cuda_runtime.h>
#include <cuda_fp16.h>
#include <cstdint>

#define B_ 4
#define S_ 2048
#define D_ 1024
#define H_ 1024

// Scratch (__device__ globals; allocation-free rule)
__device__ __align__(128) __half g_x16[B_ * S_ * D_];          // 16 MB
__device__ __align__(128) __half g_wt16[3 * D_ * H_];          // 6 MB  (W^T, [n][k])
__device__ __align__(128) __half g_q16[B_ * S_ * H_];          // 16 MB
__device__ __align__(128) __half g_k16[B_ * S_ * H_];          // 16 MB
__device__ __align__(128) __half g_vt16[B_ * H_ * S_];         // 16 MB (V^T per batch)
__device__ __align__(128) __half g_s16[(size_t)B_ * S_ * S_];  // 32 MB scores
__device__ __align__(128) __half g_p16[(size_t)B_ * S_ * S_];  // 32 MB probs

__device__ __forceinline__ uint32_t smem_u32(const void* p) {
    uint32_t a;
    asm("{ .reg .u64 t; cvta.to.shared.u64 t, %1; cvt.u32.u64 %0, t; }" : "=r"(a) : "l"(p));
    return a;
}
__device__ __forceinline__ void cp16(uint32_t dst, const void* src) {
    asm volatile("cp.async.ca.shared.global [%0], [%1], 16;" :: "r"(dst), "l"(src));
}
#define LDSM4(r0, r1, r2, r3, a)                                                   \
    asm volatile("ldmatrix.sync.aligned.m8n8.x4.shared.b16 {%0,%1,%2,%3}, [%4];"   \
                 : "=r"(r0), "=r"(r1), "=r"(r2), "=r"(r3) : "r"(a))
__device__ __forceinline__ void mma_f16(float* d, const uint32_t* a, const uint32_t* b) {
    asm volatile(
        "mma.sync.aligned.m16n8k16.row.col.f32.f16.f16.f32 "
        "{%0,%1,%2,%3}, {%4,%5,%6,%7}, {%8,%9}, {%0,%1,%2,%3};"
        : "+f"(d[0]), "+f"(d[1]), "+f"(d[2]), "+f"(d[3])
        : "r"(a[0]), "r"(a[1]), "r"(a[2]), "r"(a[3]), "r"(b[0]), "r"(b[1]));
}

// ---------------------------------------------------------------------------
// fp16 NT GEMM: C = op(alpha * (A @ B^T) + bias)
//   A [M,K] half, B [N,K] half, both K-major. Block 128x128, K-chunk 64,
//   8 warps of 64x32, m16n8k16 HMMA, ldmatrix frags, SW128 smem, 3-stage cp.async.
// EMODE: 0 fp32 out (*alpha)   1 fp16 out (+bias)
//        2 fp16 V^T out (+bias), out[b][n][t]   3 fp16 out (*alpha)
// ---------------------------------------------------------------------------
#define STG_A 16384
#define STG   32768
#define NSTG  3
#define SMEM_SZ (NSTG * STG)

template <int EMODE>
__global__ __launch_bounds__(256, 2) void hgemm(
    const __half* __restrict__ A, const __half* __restrict__ Bm,
    float* __restrict__ Cf, __half* __restrict__ Ch,
    const float* __restrict__ bias,
    float alpha, int K, int ldc,
    long sA_, long sB_, long sC_)
{
    extern __shared__ char smem[];
    const uint32_t sb = smem_u32(smem);

    const int tid  = threadIdx.x;
    const int warp = tid >> 5, lane = tid & 31;
    const int g = lane >> 2, tg = lane & 3;
    const int wm0 = (warp & 1) * 64;
    const int wn0 = (warp >> 1) * 32;
    const int m0 = blockIdx.y << 7, n0 = blockIdx.x << 7;

    const __half* pA = A + (size_t)blockIdx.z * sA_ + (size_t)m0 * K;
    const __half* pB = Bm + (size_t)blockIdx.z * sB_ + (size_t)n0 * K;

    float acc[4][4][4];
#pragma unroll
    for (int i = 0; i < 4; i++)
#pragma unroll
        for (int j = 0; j < 4; j++)
#pragma unroll
            for (int r = 0; r < 4; r++) acc[i][j][r] = 0.f;

    const int NC = K >> 6;

    auto load_stage = [&](int s, int c) {
        const int k0 = c << 6;
        const uint32_t sbase = sb + s * STG;
#pragma unroll
        for (int i = 0; i < 4; i++) {
            int idx = tid + (i << 8);              // 0..1023
            int row = idx >> 3, sub = idx & 7;     // 128 rows x 8 x 16B
            uint32_t off = row * 128 + ((sub * 16) ^ ((row & 7) << 4));
            cp16(sbase + off,         pA + (size_t)row * K + k0 + sub * 8);
            cp16(sbase + STG_A + off, pB + (size_t)row * K + k0 + sub * 8);
        }
    };

    // ldmatrix address components
    const uint32_t mask = (lane & 7) << 4;
    const int selA = (lane >> 4) << 4;             // 0 or 16 bytes
    const int selB = ((lane >> 3) & 1) << 4;
    uint32_t baseA[4], baseB[2];
#pragma unroll
    for (int mt = 0; mt < 4; mt++)
        baseA[mt] = sb + (wm0 + mt * 16 + (lane & 15)) * 128;
#pragma unroll
    for (int p = 0; p < 2; p++)
        baseB[p] = sb + STG_A + (wn0 + p * 16 + (lane & 7) + ((lane >> 4) << 3)) * 128;

    load_stage(0, 0);
    asm volatile("cp.async.commit_group;");
    load_stage(1, 1);
    asm volatile("cp.async.commit_group;");

    int s = 0;
    for (int c = 0; c < NC; c++) {
        asm volatile("cp.async.wait_group 1;");
        __syncthreads();
        if (c + 2 < NC) load_stage((s + 2) % NSTG, c + 2);
        asm volatile("cp.async.commit_group;");

        const uint32_t so = s * STG;
#pragma unroll
        for (int ks = 0; ks < 4; ks++) {
            const uint32_t kk2 = ks * 32;
            const uint32_t koA = (kk2 + selA) ^ mask;
            const uint32_t koB = (kk2 + selB) ^ mask;
            uint32_t af[4][4], bf[4][2];
#pragma unroll
            for (int mt = 0; mt < 4; mt++)
                LDSM4(af[mt][0], af[mt][1], af[mt][2], af[mt][3], baseA[mt] + so + koA);
#pragma unroll
            for (int p = 0; p < 2; p++) {
                uint32_t r0, r1, r2, r3;
                LDSM4(r0, r1, r2, r3, baseB[p] + so + koB);
                bf[2 * p][0] = r0;     bf[2 * p][1] = r1;
                bf[2 * p + 1][0] = r2; bf[2 * p + 1][1] = r3;
            }
#pragma unroll
            for (int mt = 0; mt < 4; mt++)
#pragma unroll
                for (int nt = 0; nt < 4; nt++)
                    mma_f16(acc[mt][nt], af[mt], bf[nt]);
        }
        s = (s + 1) % NSTG;
    }
    __syncthreads();   // mainloop smem dead; safe to reuse for EMODE 2

    // ---- epilogue ----
    if (EMODE == 2) {
        // stage into smem [32][72] half per warp, then coalesced V^T stores
        __half* ep = (__half*)smem + warp * 2304;
#pragma unroll
        for (int nt = 0; nt < 4; nt++) {
            const int ncol = n0 + wn0 + nt * 8 + 2 * tg;
            float2 bv = *(const float2*)&bias[ncol];
#pragma unroll
            for (int mt = 0; mt < 4; mt++)
#pragma unroll
                for (int h = 0; h < 2; h++) {
                    int ml = mt * 16 + g + h * 8;
                    int nl = nt * 8 + 2 * tg;
                    ep[nl * 72 + ml]       = __float2half_rn(acc[mt][nt][2 * h]     + bv.x);
                    ep[(nl + 1) * 72 + ml] = __float2half_rn(acc[mt][nt][2 * h + 1] + bv.y);
                }
        }
        __syncwarp();
        const int bidx = m0 >> 11;
        const int tbase = (m0 & 2047) + wm0 + (lane & 7) * 8;
#pragma unroll
        for (int i = 0; i < 8; i++) {
            int nl = i * 4 + (lane >> 3);
            int nglob = n0 + wn0 + nl;
            uint4 v = *(uint4*)&ep[nl * 72 + (lane & 7) * 8];
            *(uint4*)&Ch[((size_t)(bidx * H_ + nglob)) * S_ + tbase] = v;
        }
    } else {
#pragma unroll
        for (int nt = 0; nt < 4; nt++) {
            const int col = n0 + wn0 + nt * 8 + 2 * tg;
            float2 bv = make_float2(0.f, 0.f);
            if (EMODE == 1) bv = *(const float2*)&bias[col];
#pragma unroll
            for (int mt = 0; mt < 4; mt++)
#pragma unroll
                for (int h = 0; h < 2; h++) {
                    int r = m0 + wm0 + mt * 16 + g + h * 8;
                    float vx = acc[mt][nt][2 * h], vy = acc[mt][nt][2 * h + 1];
                    if (EMODE == 0) {
                        *(float2*)&Cf[(size_t)blockIdx.z * sC_ + (size_t)r * ldc + col] =
                            make_float2(vx * alpha, vy * alpha);
                    } else if (EMODE == 1) {
                        __half2 o = __floats2half2_rn(vx + bv.x, vy + bv.y);
                        *(__half2*)&Ch[(size_t)r * ldc + col] = o;
                    } else { // 3
                        __half2 o = __floats2half2_rn(vx * alpha, vy * alpha);
                        *(__half2*)&Ch[(size_t)blockIdx.z * sC_ + (size_t)r * ldc + col] = o;
                    }
                }
        }
    }
}

// ---------------------------------------------------------------------------
// Prep: fp32 -> fp16 copy; W transpose+convert
// ---------------------------------------------------------------------------
__global__ void f2h(const float* __restrict__ in, __half* __restrict__ out, int n8)
{
    int i = blockIdx.x * blockDim.x + threadIdx.x;
    if (i >= n8) return;
    const float4* s = (const float4*)(in + (size_t)i * 8);
    float4 a = s[0], b = s[1];
    __half2 h0 = __floats2half2_rn(a.x, a.y), h1 = __floats2half2_rn(a.z, a.w);
    __half2 h2 = __floats2half2_rn(b.x, b.y), h3 = __floats2half2_rn(b.z, b.w);
    uint4 o;
    o.x = *(uint32_t*)&h0; o.y = *(uint32_t*)&h1;
    o.z = *(uint32_t*)&h2; o.w = *(uint32_t*)&h3;
    ((uint4*)out)[i] = o;
}

__global__ void wtrans(const float* __restrict__ W, __half* __restrict__ WT)
{
    __shared__ float t[32][33];
    int x = blockIdx.x * 32 + threadIdx.x;   // n
    int y0 = blockIdx.y * 32;                // k
#pragma unroll
    for (int i = 0; i < 4; i++)
        t[threadIdx.y + i * 8][threadIdx.x] = W[(size_t)(y0 + threadIdx.y + i * 8) * H_ + x];
    __syncthreads();
    int n = blockIdx.x * 32;
#pragma unroll
    for (int i = 0; i < 4; i++)
        WT[(size_t)(n + threadIdx.y + i * 8) * D_ + y0 + threadIdx.x] =
            __float2half_rn(t[threadIdx.x][threadIdx.y + i * 8]);
}

// ---------------------------------------------------------------------------
// Softmax: fp16 scores in -> fp16 probs out, fp32 math. One block per row.
// ---------------------------------------------------------------------------
__global__ __launch_bounds__(256) void softmax16(const __half* __restrict__ Sc,
                                                 __half* __restrict__ P)
{
    const uint4* src = (const uint4*)(Sc + (size_t)blockIdx.x * 2048);
    uint4* dst = (uint4*)(P + (size_t)blockIdx.x * 2048);
    const int t = threadIdx.x;

    uint4 raw = src[t];
    __half2 h[4] = { *(__half2*)&raw.x, *(__half2*)&raw.y,
                     *(__half2*)&raw.z, *(__half2*)&raw.w };
    float v[8];
#pragma unroll
    for (int i = 0; i < 4; i++) {
        float2 f = __half22float2(h[i]);
        v[2 * i] = f.x; v[2 * i + 1] = f.y;
    }

    float m = v[0];
#pragma unroll
    for (int i = 1; i < 8; i++) m = fmaxf(m, v[i]);

    __shared__ float red[256];
    red[t] = m;
    __syncthreads();
#pragma unroll
    for (int s2 = 128; s2 > 0; s2 >>= 1) {
        if (t < s2) red[t] = fmaxf(red[t], red[t + s2]);
        __syncthreads();
    }
    m = red[0];
    __syncthreads();

    float sum = 0.f;
#pragma unroll
    for (int i = 0; i < 8; i++) { v[i] = expf(v[i] - m); sum += v[i]; }

    red[t] = sum;
    __syncthreads();
#pragma unroll
    for (int s2 = 128; s2 > 0; s2 >>= 1) {
        if (t < s2) red[t] += red[t + s2];
        __syncthreads();
    }
    float inv = 1.f / red[0];

    __half2 o0 = __floats2half2_rn(v[0] * inv, v[1] * inv);
    __half2 o1 = __floats2half2_rn(v[2] * inv, v[3] * inv);
    __half2 o2 = __floats2half2_rn(v[4] * inv, v[5] * inv);
    __half2 o3 = __floats2half2_rn(v[6] * inv, v[7] * inv);
    uint4 o;
    o.x = *(uint32_t*)&o0; o.y = *(uint32_t*)&o1;
    o.z = *(uint32_t*)&o2; o.w = *(uint32_t*)&o3;
    dst[t] = o;
}

// ---------------------------------------------------------------------------
extern "C" void kernel_launch(void* const* d_in, const int* in_sizes, int n_in,
                              void* d_out, int out_size)
{
    const float* x  = (const float*)d_in[0];
    const float* Wq = (const float*)d_in[1];
    const float* bq = (const float*)d_in[2];
    const float* Wk = (const float*)d_in[3];
    const float* bk = (const float*)d_in[4];
    const float* Wv = (const float*)d_in[5];
    const float* bv = (const float*)d_in[6];
    float* out = (float*)d_out;

    __half *x16, *wt16, *q16, *k16, *vt16, *s16, *p16;
    cudaGetSymbolAddress((void**)&x16, g_x16);
    cudaGetSymbolAddress((void**)&wt16, g_wt16);
    cudaGetSymbolAddress((void**)&q16, g_q16);
    cudaGetSymbolAddress((void**)&k16, g_k16);
    cudaGetSymbolAddress((void**)&vt16, g_vt16);
    cudaGetSymbolAddress((void**)&s16, g_s16);
    cudaGetSymbolAddress((void**)&p16, g_p16);

    static int init = 0;
    if (!init) {
        cudaFuncSetAttribute(hgemm<0>, cudaFuncAttributeMaxDynamicSharedMemorySize, SMEM_SZ);
        cudaFuncSetAttribute(hgemm<1>, cudaFuncAttributeMaxDynamicSharedMemorySize, SMEM_SZ);
        cudaFuncSetAttribute(hgemm<2>, cudaFuncAttributeMaxDynamicSharedMemorySize, SMEM_SZ);
        cudaFuncSetAttribute(hgemm<3>, cudaFuncAttributeMaxDynamicSharedMemorySize, SMEM_SZ);
        init = 1;
    }

    const float inv_dk = 0.03125f;   // 1/sqrt(1024)

    // prep
    f2h<<<(1048576 + 255) / 256, 256>>>(x, x16, 1048576);
    wtrans<<<dim3(32, 32), dim3(32, 8)>>>(Wq, wt16);
    wtrans<<<dim3(32, 32), dim3(32, 8)>>>(Wk, wt16 + 1048576);
    wtrans<<<dim3(32, 32), dim3(32, 8)>>>(Wv, wt16 + 2097152);

    // projections: [8192,1024] @ W^T[1024,1024] (NT) + bias
    dim3 gProj(H_ / 128, (B_ * S_) / 128, 1);
    hgemm<1><<<gProj, 256, SMEM_SZ>>>(x16, wt16,           nullptr, q16, bq,
                                      1.f, D_, H_, 0, 0, 0);
    hgemm<1><<<gProj, 256, SMEM_SZ>>>(x16, wt16 + 1048576, nullptr, k16, bk,
                                      1.f, D_, H_, 0, 0, 0);
    hgemm<2><<<gProj, 256, SMEM_SZ>>>(x16, wt16 + 2097152, nullptr, vt16, bv,
                                      1.f, D_, H_, 0, 0, 0);

    // scores[b] = (q @ k^T)/32 -> fp16 (NT, per batch)
    dim3 gScore(S_ / 128, S_ / 128, B_);
    hgemm<3><<<gScore, 256, SMEM_SZ>>>(q16, k16, nullptr, s16, nullptr,
                                       inv_dk, H_, S_,
                                       (long)S_ * H_, (long)S_ * H_, (long)S_ * S_);

    softmax16<<<B_ * S_, 256>>>(s16, p16);

    // out[b] = probs @ V (NT against V^T, per batch) -> fp32
    dim3 gPV(H_ / 128, S_ / 128, B_);
    hgemm<0><<<gPV, 256, SMEM_SZ>>>(p16, vt16, out, nullptr, nullptr,
                                    1.f, S_, H_,
                                    (long)S_ * S_, (long)S_ * H_, (long)S_ * H_);
}